// round 1
// baseline (speedup 1.0000x reference)
#include <cuda_runtime.h>
#include <math.h>

#define N_NODES 100000
#define E_EDGES 1600000
#define ET      (E_EDGES + N_NODES)   // 1,700,000 edges incl. self-loops
#define F_IN    128
#define HID     32
#define HEADS   4
#define C1      (HEADS * HID)         // 128
#define OUT_C   16

// ---------------- scratch (static device globals; no allocs allowed) --------
__device__ float g_h1  [N_NODES * C1];      // x @ W1
__device__ float g_als1[N_NODES * HEADS];   // per-node src logit, layer 1
__device__ float g_ald1[N_NODES * HEADS];   // per-node dst logit, layer 1
__device__ float g_expw1[(size_t)ET * HEADS];
__device__ float g_sum1[N_NODES * HEADS];
__device__ float g_acc1[N_NODES * C1];      // layer-1 aggregation
__device__ float g_h1p [N_NODES * C1];      // elu(acc1+b1), column-permuted
__device__ float g_h2  [N_NODES * OUT_C];
__device__ float g_als2[N_NODES];
__device__ float g_ald2[N_NODES];
__device__ float g_expw2[ET];
__device__ float g_sum2[N_NODES];
__device__ float g_acc2[N_NODES * OUT_C];

// ---------------- K0: zero accumulators -------------------------------------
__global__ void zero_kernel() {
    int i = blockIdx.x * blockDim.x + threadIdx.x;
    if (i < N_NODES * C1)    g_acc1[i] = 0.f;
    if (i < N_NODES * HEADS) g_sum1[i] = 0.f;
    if (i < N_NODES * OUT_C) g_acc2[i] = 0.f;
    if (i < N_NODES)         g_sum2[i] = 0.f;
}

// ---------------- K1: h1 = x @ W1  (tiled SMEM GEMM, fp32) ------------------
#define BM 64
#define BN 128
#define BK 16
__global__ void gemm1_kernel(const float* __restrict__ A,
                             const float* __restrict__ W) {
    __shared__ float As[BK][BM];      // transposed A tile
    __shared__ float Bs[BK][BN];
    int tid = threadIdx.x;            // 256 threads
    int tx = tid & 15, ty = tid >> 4; // 16x16
    int m0 = blockIdx.x * BM;
    float acc[4][8];
    #pragma unroll
    for (int r = 0; r < 4; r++)
        #pragma unroll
        for (int j = 0; j < 8; j++) acc[r][j] = 0.f;

    for (int k0 = 0; k0 < F_IN; k0 += BK) {
        // A tile: 64x16 = 256 float4
        {
            int row = tid >> 2;
            int kq  = (tid & 3) * 4;
            float4 v = make_float4(0.f, 0.f, 0.f, 0.f);
            if (m0 + row < N_NODES)
                v = *(const float4*)&A[(size_t)(m0 + row) * F_IN + k0 + kq];
            As[kq + 0][row] = v.x; As[kq + 1][row] = v.y;
            As[kq + 2][row] = v.z; As[kq + 3][row] = v.w;
        }
        // B tile: 16x128 = 512 float4, 2 per thread
        #pragma unroll
        for (int i = 0; i < 2; i++) {
            int idx = tid + i * 256;
            int row = idx >> 5;
            int cq  = (idx & 31) * 4;
            *(float4*)&Bs[row][cq] = *(const float4*)&W[(size_t)(k0 + row) * BN + cq];
        }
        __syncthreads();
        #pragma unroll
        for (int k = 0; k < BK; k++) {
            float4 a4  = *(float4*)&As[k][ty * 4];
            float4 b40 = *(float4*)&Bs[k][tx * 8];
            float4 b41 = *(float4*)&Bs[k][tx * 8 + 4];
            float a[4] = {a4.x, a4.y, a4.z, a4.w};
            float b[8] = {b40.x, b40.y, b40.z, b40.w, b41.x, b41.y, b41.z, b41.w};
            #pragma unroll
            for (int r = 0; r < 4; r++)
                #pragma unroll
                for (int j = 0; j < 8; j++) acc[r][j] += a[r] * b[j];
        }
        __syncthreads();
    }
    #pragma unroll
    for (int r = 0; r < 4; r++) {
        int m = m0 + ty * 4 + r;
        if (m < N_NODES) {
            *(float4*)&g_h1[(size_t)m * C1 + tx * 8] =
                make_float4(acc[r][0], acc[r][1], acc[r][2], acc[r][3]);
            *(float4*)&g_h1[(size_t)m * C1 + tx * 8 + 4] =
                make_float4(acc[r][4], acc[r][5], acc[r][6], acc[r][7]);
        }
    }
}

// ---------------- K1b: per-node attention logits (layer 1) ------------------
__global__ void al1_kernel(const float* __restrict__ a_s,
                           const float* __restrict__ a_d) {
    int n    = blockIdx.x * 8 + (threadIdx.x >> 5);
    int lane = threadIdx.x & 31;
    if (n >= N_NODES) return;
    float4 hv = *(const float4*)&g_h1[(size_t)n * C1 + lane * 4];
    float4 s4 = *(const float4*)&a_s[lane * 4];   // [4,32] flat == channel index
    float4 d4 = *(const float4*)&a_d[lane * 4];
    float vs = hv.x * s4.x + hv.y * s4.y + hv.z * s4.z + hv.w * s4.w;
    float vd = hv.x * d4.x + hv.y * d4.y + hv.z * d4.z + hv.w * d4.w;
    #pragma unroll
    for (int m = 4; m > 0; m >>= 1) {
        vs += __shfl_xor_sync(0xffffffffu, vs, m, 8);
        vd += __shfl_xor_sync(0xffffffffu, vd, m, 8);
    }
    if ((lane & 7) == 0) {
        int h = lane >> 3;
        g_als1[n * HEADS + h] = vs;
        g_ald1[n * HEADS + h] = vd;
    }
}

// ---------------- K2: edge logits + denominator (layer 1) -------------------
__global__ void edge1a_kernel(const int* __restrict__ ei) {
    int e = blockIdx.x * blockDim.x + threadIdx.x;
    if (e >= ET) return;
    int src, dst;
    if (e < E_EDGES) { src = ei[e]; dst = ei[E_EDGES + e]; }
    else             { src = dst = e - E_EDGES; }
    float4 as = *(const float4*)&g_als1[src * HEADS];
    float4 ad = *(const float4*)&g_ald1[dst * HEADS];
    float z0 = as.x + ad.x; z0 = z0 > 0.f ? z0 : 0.2f * z0;
    float z1 = as.y + ad.y; z1 = z1 > 0.f ? z1 : 0.2f * z1;
    float z2 = as.z + ad.z; z2 = z2 > 0.f ? z2 : 0.2f * z2;
    float z3 = as.w + ad.w; z3 = z3 > 0.f ? z3 : 0.2f * z3;
    float e0 = expf(z0), e1 = expf(z1), e2 = expf(z2), e3 = expf(z3);
    *(float4*)&g_expw1[(size_t)e * HEADS] = make_float4(e0, e1, e2, e3);
    atomicAdd(&g_sum1[dst * HEADS + 0], e0);
    atomicAdd(&g_sum1[dst * HEADS + 1], e1);
    atomicAdd(&g_sum1[dst * HEADS + 2], e2);
    atomicAdd(&g_sum1[dst * HEADS + 3], e3);
}

// ---------------- K3: weighted message scatter (layer 1) --------------------
// warp per edge: lanes cover the 128 channels as float4.
__global__ void edge1b_kernel(const int* __restrict__ ei) {
    int e = blockIdx.x * 8 + (threadIdx.x >> 5);
    if (e >= ET) return;
    int lane = threadIdx.x & 31;
    int src, dst;
    if (e < E_EDGES) { src = ei[e]; dst = ei[E_EDGES + e]; }
    else             { src = dst = e - E_EDGES; }
    int h   = lane >> 3;
    float w = g_expw1[(size_t)e * HEADS + h] /
              (g_sum1[dst * HEADS + h] + 1e-16f);
    float4 hv = *(const float4*)&g_h1[(size_t)src * C1 + lane * 4];
    float* o  = &g_acc1[(size_t)dst * C1 + lane * 4];
    atomicAdd(o + 0, hv.x * w);
    atomicAdd(o + 1, hv.y * w);
    atomicAdd(o + 2, hv.z * w);
    atomicAdd(o + 3, hv.w * w);
}

// ---------------- K4: bias + ELU + strided-column regroup -------------------
__global__ void post1_kernel(const float* __restrict__ b1) {
    int idx = blockIdx.x * blockDim.x + threadIdx.x;   // N * 32
    if (idx >= N_NODES * 32) return;
    int n  = idx >> 5;
    int c0 = (idx & 31) * 4;
    float4 v = *(const float4*)&g_acc1[(size_t)n * C1 + c0];
    float4 b = *(const float4*)&b1[c0];
    float r[4] = {v.x + b.x, v.y + b.y, v.z + b.z, v.w + b.w};
    #pragma unroll
    for (int i = 0; i < 4; i++) {
        float t = r[i];
        t = t > 0.f ? t : expm1f(t);
        int c = c0 + i;
        int j = (c & 3) * 32 + (c >> 2);      // h_new[:, i*32+k] = h_old[:, 4k+i]
        g_h1p[(size_t)n * C1 + j] = t;
    }
}

// ---------------- K5: h2 = h1p @ W2 (+ layer-2 logits) ----------------------
__global__ void gemm2_kernel(const float* __restrict__ W2,
                             const float* __restrict__ a_s,
                             const float* __restrict__ a_d) {
    __shared__ float Ws[128 * 16];
    __shared__ float Hs[16][129];
    __shared__ float as2[16], ad2[16];
    int tid = threadIdx.x;            // 256
    int tx = tid & 15, ty = tid >> 4;
    int n0 = blockIdx.x * 16;
    for (int i = tid; i < 128 * 16; i += 256) Ws[i] = W2[i];
    if (tid < 16) { as2[tid] = a_s[tid]; ad2[tid] = a_d[tid]; }
    for (int i = tid; i < 16 * 128; i += 256) {
        int r = i >> 7, c = i & 127;
        Hs[r][c] = (n0 + r < N_NODES) ? g_h1p[(size_t)(n0 + r) * C1 + c] : 0.f;
    }
    __syncthreads();
    float v = 0.f;
    #pragma unroll
    for (int k = 0; k < 128; k++) v += Hs[ty][k] * Ws[k * 16 + tx];
    float vs = v * as2[tx], vd = v * ad2[tx];
    #pragma unroll
    for (int m = 8; m > 0; m >>= 1) {
        vs += __shfl_xor_sync(0xffffffffu, vs, m, 16);
        vd += __shfl_xor_sync(0xffffffffu, vd, m, 16);
    }
    int n = n0 + ty;
    if (n < N_NODES) {
        g_h2[n * OUT_C + tx] = v;
        if (tx == 0) { g_als2[n] = vs; g_ald2[n] = vd; }
    }
}

// ---------------- K6: edge logits + denominator (layer 2) -------------------
__global__ void edge2a_kernel(const int* __restrict__ ei) {
    int e = blockIdx.x * blockDim.x + threadIdx.x;
    if (e >= ET) return;
    int src, dst;
    if (e < E_EDGES) { src = ei[e]; dst = ei[E_EDGES + e]; }
    else             { src = dst = e - E_EDGES; }
    float z = g_als2[src] + g_ald2[dst];
    z = z > 0.f ? z : 0.2f * z;
    float ew = expf(z);
    g_expw2[e] = ew;
    atomicAdd(&g_sum2[dst], ew);
}

// ---------------- K7: weighted message scatter (layer 2) --------------------
__global__ void edge2b_kernel(const int* __restrict__ ei) {
    int idx = blockIdx.x * blockDim.x + threadIdx.x;   // 4 threads/edge
    int e = idx >> 2;
    if (e >= ET) return;
    int q = idx & 3;
    int src, dst;
    if (e < E_EDGES) { src = ei[e]; dst = ei[E_EDGES + e]; }
    else             { src = dst = e - E_EDGES; }
    float w = g_expw2[e] / (g_sum2[dst] + 1e-16f);
    float4 hv = *(const float4*)&g_h2[src * OUT_C + q * 4];
    float* o  = &g_acc2[dst * OUT_C + q * 4];
    atomicAdd(o + 0, hv.x * w);
    atomicAdd(o + 1, hv.y * w);
    atomicAdd(o + 2, hv.z * w);
    atomicAdd(o + 3, hv.w * w);
}

// ---------------- K8: bias + log_softmax ------------------------------------
__global__ void final_kernel(const float* __restrict__ b2,
                             float* __restrict__ out) {
    int tid = threadIdx.x;
    int o = tid & 15;
    int n = blockIdx.x * 16 + (tid >> 4);
    if (n >= N_NODES) return;   // uniform over each 16-lane group
    float v = g_acc2[n * OUT_C + o] + b2[o];
    float m = v;
    #pragma unroll
    for (int s = 8; s > 0; s >>= 1)
        m = fmaxf(m, __shfl_xor_sync(0xffffffffu, m, s, 16));
    float e = expf(v - m);
    float sum = e;
    #pragma unroll
    for (int s = 8; s > 0; s >>= 1)
        sum += __shfl_xor_sync(0xffffffffu, sum, s, 16);
    out[n * OUT_C + o] = v - m - logf(sum);
}

// ---------------- launcher ---------------------------------------------------
extern "C" void kernel_launch(void* const* d_in, const int* in_sizes, int n_in,
                              void* d_out, int out_size) {
    const float* x      = (const float*)d_in[0];
    const int*   ei     = (const int*)  d_in[1];
    const float* W1     = (const float*)d_in[2];
    const float* a_src1 = (const float*)d_in[3];
    const float* a_dst1 = (const float*)d_in[4];
    const float* b1     = (const float*)d_in[5];
    const float* W2     = (const float*)d_in[6];
    const float* a_src2 = (const float*)d_in[7];
    const float* a_dst2 = (const float*)d_in[8];
    const float* b2     = (const float*)d_in[9];
    float* out = (float*)d_out;

    zero_kernel  <<<(N_NODES * C1 + 255) / 256, 256>>>();
    gemm1_kernel <<<(N_NODES + BM - 1) / BM, 256>>>(x, W1);
    al1_kernel   <<<(N_NODES + 7) / 8, 256>>>(a_src1, a_dst1);
    edge1a_kernel<<<(ET + 255) / 256, 256>>>(ei);
    edge1b_kernel<<<(ET + 7) / 8, 256>>>(ei);
    post1_kernel <<<(N_NODES * 32 + 255) / 256, 256>>>(b1);
    gemm2_kernel <<<(N_NODES + 15) / 16, 256>>>(W2, a_src2, a_dst2);
    edge2a_kernel<<<(ET + 255) / 256, 256>>>(ei);
    edge2b_kernel<<<(ET * 4 + 255) / 256, 256>>>(ei);
    final_kernel <<<(N_NODES + 15) / 16, 256>>>(b2, out);
}

// round 2
// speedup vs baseline: 1.5217x; 1.5217x over previous
#include <cuda_runtime.h>
#include <math.h>

#define N_NODES 100000
#define E_EDGES 1600000
#define ET      (E_EDGES + N_NODES)   // 1,700,000 edges incl. self-loops
#define F_IN    128
#define HID     32
#define HEADS   4
#define C1      (HEADS * HID)         // 128
#define OUT_C   16

// ---------------- scratch (static device globals; no allocs allowed) --------
__device__ float g_h1  [N_NODES * C1];      // x @ W1
__device__ float g_als1[N_NODES * HEADS];   // per-node src logit, layer 1
__device__ float g_ald1[N_NODES * HEADS];   // per-node dst logit, layer 1
__device__ float g_sum1[N_NODES * HEADS];   // unnormalized softmax denominators
__device__ float g_acc1[N_NODES * C1];      // layer-1 unnormalized aggregation
__device__ float g_h1p [N_NODES * C1];      // elu(acc1/sum1+b1), column-permuted
__device__ float g_h2  [N_NODES * OUT_C];
__device__ float g_als2[N_NODES];
__device__ float g_ald2[N_NODES];
__device__ float g_sum2[N_NODES];
__device__ float g_acc2[N_NODES * OUT_C];

// one L2 atomic op per 16B instead of 4 scalar ops (sm_90+ vector red)
__device__ __forceinline__ void red4(float* p, float a, float b, float c, float d) {
    asm volatile("red.global.add.v4.f32 [%0], {%1,%2,%3,%4};"
                 :: "l"(p), "f"(a), "f"(b), "f"(c), "f"(d) : "memory");
}

// ---------------- K0: zero accumulators -------------------------------------
__global__ void zero_kernel() {
    int i = blockIdx.x * blockDim.x + threadIdx.x;
    if (i < N_NODES * C1)    g_acc1[i] = 0.f;
    if (i < N_NODES * HEADS) g_sum1[i] = 0.f;
    if (i < N_NODES * OUT_C) g_acc2[i] = 0.f;
    if (i < N_NODES)         g_sum2[i] = 0.f;
}

// ---------------- K1: h1 = x @ W1  (tiled SMEM GEMM, fp32) ------------------
#define BM 64
#define BN 128
#define BK 16
__global__ void gemm1_kernel(const float* __restrict__ A,
                             const float* __restrict__ W) {
    __shared__ float As[BK][BM];      // transposed A tile
    __shared__ float Bs[BK][BN];
    int tid = threadIdx.x;            // 256 threads
    int tx = tid & 15, ty = tid >> 4; // 16x16
    int m0 = blockIdx.x * BM;
    float acc[4][8];
    #pragma unroll
    for (int r = 0; r < 4; r++)
        #pragma unroll
        for (int j = 0; j < 8; j++) acc[r][j] = 0.f;

    for (int k0 = 0; k0 < F_IN; k0 += BK) {
        {
            int row = tid >> 2;
            int kq  = (tid & 3) * 4;
            float4 v = make_float4(0.f, 0.f, 0.f, 0.f);
            if (m0 + row < N_NODES)
                v = *(const float4*)&A[(size_t)(m0 + row) * F_IN + k0 + kq];
            As[kq + 0][row] = v.x; As[kq + 1][row] = v.y;
            As[kq + 2][row] = v.z; As[kq + 3][row] = v.w;
        }
        #pragma unroll
        for (int i = 0; i < 2; i++) {
            int idx = tid + i * 256;
            int row = idx >> 5;
            int cq  = (idx & 31) * 4;
            *(float4*)&Bs[row][cq] = *(const float4*)&W[(size_t)(k0 + row) * BN + cq];
        }
        __syncthreads();
        #pragma unroll
        for (int k = 0; k < BK; k++) {
            float4 a4  = *(float4*)&As[k][ty * 4];
            float4 b40 = *(float4*)&Bs[k][tx * 8];
            float4 b41 = *(float4*)&Bs[k][tx * 8 + 4];
            float a[4] = {a4.x, a4.y, a4.z, a4.w};
            float b[8] = {b40.x, b40.y, b40.z, b40.w, b41.x, b41.y, b41.z, b41.w};
            #pragma unroll
            for (int r = 0; r < 4; r++)
                #pragma unroll
                for (int j = 0; j < 8; j++) acc[r][j] += a[r] * b[j];
        }
        __syncthreads();
    }
    #pragma unroll
    for (int r = 0; r < 4; r++) {
        int m = m0 + ty * 4 + r;
        if (m < N_NODES) {
            *(float4*)&g_h1[(size_t)m * C1 + tx * 8] =
                make_float4(acc[r][0], acc[r][1], acc[r][2], acc[r][3]);
            *(float4*)&g_h1[(size_t)m * C1 + tx * 8 + 4] =
                make_float4(acc[r][4], acc[r][5], acc[r][6], acc[r][7]);
        }
    }
}

// ---------------- K1b: per-node attention logits (layer 1) ------------------
__global__ void al1_kernel(const float* __restrict__ a_s,
                           const float* __restrict__ a_d) {
    int n    = blockIdx.x * 8 + (threadIdx.x >> 5);
    int lane = threadIdx.x & 31;
    if (n >= N_NODES) return;
    float4 hv = *(const float4*)&g_h1[(size_t)n * C1 + lane * 4];
    float4 s4 = *(const float4*)&a_s[lane * 4];   // [4,32] flat == channel index
    float4 d4 = *(const float4*)&a_d[lane * 4];
    float vs = hv.x * s4.x + hv.y * s4.y + hv.z * s4.z + hv.w * s4.w;
    float vd = hv.x * d4.x + hv.y * d4.y + hv.z * d4.z + hv.w * d4.w;
    #pragma unroll
    for (int m = 4; m > 0; m >>= 1) {
        vs += __shfl_xor_sync(0xffffffffu, vs, m, 8);
        vd += __shfl_xor_sync(0xffffffffu, vd, m, 8);
    }
    if ((lane & 7) == 0) {
        int h = lane >> 3;
        g_als1[n * HEADS + h] = vs;
        g_ald1[n * HEADS + h] = vd;
    }
}

// ---------------- K2: FUSED layer-1 edge pass -------------------------------
// warp per edge. Unnormalized weights: acc1[dst] += w_h * h1[src],
// sum1[dst] += w. Normalization happens in post1.
__global__ void edge1_kernel(const int* __restrict__ ei) {
    int e = blockIdx.x * 8 + (threadIdx.x >> 5);
    if (e >= ET) return;
    int lane = threadIdx.x & 31;
    int src, dst;
    if (e < E_EDGES) { src = ei[e]; dst = ei[E_EDGES + e]; }
    else             { src = dst = e - E_EDGES; }

    float4 as = *(const float4*)&g_als1[src * HEADS];
    float4 ad = *(const float4*)&g_ald1[dst * HEADS];
    // lane computes the exp for head component (lane & 3); shuffles distribute
    int c = lane & 3;
    float z = (c == 0) ? as.x + ad.x :
              (c == 1) ? as.y + ad.y :
              (c == 2) ? as.z + ad.z : as.w + ad.w;
    z = z > 0.f ? z : 0.2f * z;
    float ex = __expf(z);
    float w  = __shfl_sync(0xffffffffu, ex, lane >> 3);   // head of this lane
    float e0 = __shfl_sync(0xffffffffu, ex, 0);
    float e1 = __shfl_sync(0xffffffffu, ex, 1);
    float e2 = __shfl_sync(0xffffffffu, ex, 2);
    float e3 = __shfl_sync(0xffffffffu, ex, 3);

    float4 hv = *(const float4*)&g_h1[(size_t)src * C1 + lane * 4];
    red4(&g_acc1[(size_t)dst * C1 + lane * 4],
         hv.x * w, hv.y * w, hv.z * w, hv.w * w);
    if (lane == 0)
        red4(&g_sum1[dst * HEADS], e0, e1, e2, e3);
}

// ---------------- K3: normalize + bias + ELU + strided-column regroup -------
__global__ void post1_kernel(const float* __restrict__ b1) {
    int idx = blockIdx.x * blockDim.x + threadIdx.x;   // N * 32
    if (idx >= N_NODES * 32) return;
    int n  = idx >> 5;
    int c0 = (idx & 31) * 4;                 // 4 channels, same head
    int h  = c0 >> 5;
    float inv = 1.f / (g_sum1[n * HEADS + h] + 1e-16f);
    float4 v = *(const float4*)&g_acc1[(size_t)n * C1 + c0];
    float4 b = *(const float4*)&b1[c0];
    float r[4] = {v.x * inv + b.x, v.y * inv + b.y,
                  v.z * inv + b.z, v.w * inv + b.w};
    #pragma unroll
    for (int i = 0; i < 4; i++) {
        float t = r[i];
        t = t > 0.f ? t : expm1f(t);
        int cc = c0 + i;
        int j = (cc & 3) * 32 + (cc >> 2);   // h_new[:, i*32+k] = h_old[:, 4k+i]
        g_h1p[(size_t)n * C1 + j] = t;
    }
}

// ---------------- K4: h2 = h1p @ W2 (+ layer-2 logits) ----------------------
__global__ void gemm2_kernel(const float* __restrict__ W2,
                             const float* __restrict__ a_s,
                             const float* __restrict__ a_d) {
    __shared__ float Ws[128 * 16];
    __shared__ float Hs[16][129];
    __shared__ float as2[16], ad2[16];
    int tid = threadIdx.x;            // 256
    int tx = tid & 15, ty = tid >> 4;
    int n0 = blockIdx.x * 16;
    for (int i = tid; i < 128 * 16; i += 256) Ws[i] = W2[i];
    if (tid < 16) { as2[tid] = a_s[tid]; ad2[tid] = a_d[tid]; }
    for (int i = tid; i < 16 * 128; i += 256) {
        int r = i >> 7, cidx = i & 127;
        Hs[r][cidx] = (n0 + r < N_NODES) ? g_h1p[(size_t)(n0 + r) * C1 + cidx] : 0.f;
    }
    __syncthreads();
    float v = 0.f;
    #pragma unroll
    for (int k = 0; k < 128; k++) v += Hs[ty][k] * Ws[k * 16 + tx];
    float vs = v * as2[tx], vd = v * ad2[tx];
    #pragma unroll
    for (int m = 8; m > 0; m >>= 1) {
        vs += __shfl_xor_sync(0xffffffffu, vs, m, 16);
        vd += __shfl_xor_sync(0xffffffffu, vd, m, 16);
    }
    int n = n0 + ty;
    if (n < N_NODES) {
        g_h2[n * OUT_C + tx] = v;
        if (tx == 0) { g_als2[n] = vs; g_ald2[n] = vd; }
    }
}

// ---------------- K5: FUSED layer-2 edge pass (4 lanes/edge) ----------------
__global__ void edge2_kernel(const int* __restrict__ ei) {
    int idx = blockIdx.x * blockDim.x + threadIdx.x;
    int e = idx >> 2;
    if (e >= ET) return;
    int q = idx & 3;
    int src, dst;
    if (e < E_EDGES) { src = ei[e]; dst = ei[E_EDGES + e]; }
    else             { src = dst = e - E_EDGES; }
    float z = g_als2[src] + g_ald2[dst];
    z = z > 0.f ? z : 0.2f * z;
    float w = __expf(z);
    float4 hv = *(const float4*)&g_h2[src * OUT_C + q * 4];
    red4(&g_acc2[dst * OUT_C + q * 4],
         hv.x * w, hv.y * w, hv.z * w, hv.w * w);
    if (q == 0) atomicAdd(&g_sum2[dst], w);
}

// ---------------- K6: normalize + bias + log_softmax ------------------------
__global__ void final_kernel(const float* __restrict__ b2,
                             float* __restrict__ out) {
    int tid = threadIdx.x;
    int o = tid & 15;
    int n = blockIdx.x * 16 + (tid >> 4);
    if (n >= N_NODES) return;   // uniform over each 16-lane group
    float inv = 1.f / (g_sum2[n] + 1e-16f);
    float v = g_acc2[n * OUT_C + o] * inv + b2[o];
    float m = v;
    #pragma unroll
    for (int s = 8; s > 0; s >>= 1)
        m = fmaxf(m, __shfl_xor_sync(0xffffffffu, m, s, 16));
    float ev = __expf(v - m);
    float sum = ev;
    #pragma unroll
    for (int s = 8; s > 0; s >>= 1)
        sum += __shfl_xor_sync(0xffffffffu, sum, s, 16);
    out[n * OUT_C + o] = v - m - logf(sum);
}

// ---------------- launcher ---------------------------------------------------
extern "C" void kernel_launch(void* const* d_in, const int* in_sizes, int n_in,
                              void* d_out, int out_size) {
    const float* x      = (const float*)d_in[0];
    const int*   ei     = (const int*)  d_in[1];
    const float* W1     = (const float*)d_in[2];
    const float* a_src1 = (const float*)d_in[3];
    const float* a_dst1 = (const float*)d_in[4];
    const float* b1     = (const float*)d_in[5];
    const float* W2     = (const float*)d_in[6];
    const float* a_src2 = (const float*)d_in[7];
    const float* a_dst2 = (const float*)d_in[8];
    const float* b2     = (const float*)d_in[9];
    float* out = (float*)d_out;

    zero_kernel  <<<(N_NODES * C1 + 255) / 256, 256>>>();
    gemm1_kernel <<<(N_NODES + BM - 1) / BM, 256>>>(x, W1);
    al1_kernel   <<<(N_NODES + 7) / 8, 256>>>(a_src1, a_dst1);
    edge1_kernel <<<(ET + 7) / 8, 256>>>(ei);
    post1_kernel <<<(N_NODES * 32 + 255) / 256, 256>>>(b1);
    gemm2_kernel <<<(N_NODES + 15) / 16, 256>>>(W2, a_src2, a_dst2);
    edge2_kernel <<<(ET * 4 + 255) / 256, 256>>>(ei);
    final_kernel <<<(N_NODES + 15) / 16, 256>>>(b2, out);
}

// round 3
// speedup vs baseline: 2.3875x; 1.5690x over previous
#include <cuda_runtime.h>
#include <math.h>

#define N_NODES 100000
#define E_EDGES 1600000
#define ET      (E_EDGES + N_NODES)   // 1,700,000 edges incl. self-loops
#define F_IN    128
#define HID     32
#define HEADS   4
#define C1      (HEADS * HID)         // 128
#define OUT_C   16
#define CHUNK   512
#define NCH     ((N_NODES + CHUNK - 1) / CHUNK)   // 196

// ---------------- scratch (static device globals; no allocs allowed) --------
__device__ float g_h1  [N_NODES * C1];      // x @ W1
__device__ float g_als1[N_NODES * HEADS];
__device__ float g_ald1[N_NODES * HEADS];
__device__ float g_h1p [N_NODES * C1];      // layer-1 output, column-permuted
__device__ float g_h2  [N_NODES * OUT_C];
__device__ float g_als2[N_NODES];
__device__ float g_ald2[N_NODES];

// CSR scratch
__device__ int g_cnt   [N_NODES];
__device__ int g_loc   [N_NODES];           // per-chunk exclusive scan
__device__ int g_chsum [NCH];
__device__ int g_choff [NCH];
__device__ int g_rowptr[N_NODES + 1];
__device__ int g_cursor[N_NODES];
__device__ int g_csr_src[ET];

// ---------------- CSR build --------------------------------------------------
__global__ void zero_cnt_kernel() {
    int i = blockIdx.x * blockDim.x + threadIdx.x;
    if (i < N_NODES) g_cnt[i] = 0;
}

__global__ void hist_kernel(const int* __restrict__ ei) {
    int e = blockIdx.x * blockDim.x + threadIdx.x;
    if (e >= ET) return;
    int dst = (e < E_EDGES) ? ei[E_EDGES + e] : e - E_EDGES;
    atomicAdd(&g_cnt[dst], 1);
}

// per-chunk exclusive scan (Hillis-Steele over 512)
__global__ void scan1_kernel() {
    __shared__ int s[CHUNK];
    int t = threadIdx.x;
    int i = blockIdx.x * CHUNK + t;
    int v = (i < N_NODES) ? g_cnt[i] : 0;
    s[t] = v;
    __syncthreads();
    #pragma unroll
    for (int off = 1; off < CHUNK; off <<= 1) {
        int x = (t >= off) ? s[t - off] : 0;
        __syncthreads();
        s[t] += x;
        __syncthreads();
    }
    if (i < N_NODES) g_loc[i] = s[t] - v;
    if (t == CHUNK - 1) g_chsum[blockIdx.x] = s[t];
}

__global__ void scan2_kernel() {
    __shared__ int s[256];
    int t = threadIdx.x;
    int v = (t < NCH) ? g_chsum[t] : 0;
    s[t] = v;
    __syncthreads();
    #pragma unroll
    for (int off = 1; off < 256; off <<= 1) {
        int x = (t >= off) ? s[t - off] : 0;
        __syncthreads();
        s[t] += x;
        __syncthreads();
    }
    if (t < NCH) g_choff[t] = s[t] - v;
}

__global__ void scan3_kernel() {
    int i = blockIdx.x * blockDim.x + threadIdx.x;
    if (i < N_NODES) {
        int r = g_loc[i] + g_choff[i / CHUNK];
        g_rowptr[i] = r;
        g_cursor[i] = r;
    }
    if (i == 0) g_rowptr[N_NODES] = ET;
}

__global__ void scatter_kernel(const int* __restrict__ ei) {
    int e = blockIdx.x * blockDim.x + threadIdx.x;
    if (e >= ET) return;
    int src, dst;
    if (e < E_EDGES) { src = ei[e]; dst = ei[E_EDGES + e]; }
    else             { src = dst = e - E_EDGES; }
    int pos = atomicAdd(&g_cursor[dst], 1);
    g_csr_src[pos] = src;
}

// ---------------- K1: h1 = x @ W1  (tiled SMEM GEMM, fp32) ------------------
#define BM 64
#define BN 128
#define BK 16
__global__ void gemm1_kernel(const float* __restrict__ A,
                             const float* __restrict__ W) {
    __shared__ float As[BK][BM];
    __shared__ float Bs[BK][BN];
    int tid = threadIdx.x;            // 256 threads
    int tx = tid & 15, ty = tid >> 4;
    int m0 = blockIdx.x * BM;
    float acc[4][8];
    #pragma unroll
    for (int r = 0; r < 4; r++)
        #pragma unroll
        for (int j = 0; j < 8; j++) acc[r][j] = 0.f;

    for (int k0 = 0; k0 < F_IN; k0 += BK) {
        {
            int row = tid >> 2;
            int kq  = (tid & 3) * 4;
            float4 v = make_float4(0.f, 0.f, 0.f, 0.f);
            if (m0 + row < N_NODES)
                v = *(const float4*)&A[(size_t)(m0 + row) * F_IN + k0 + kq];
            As[kq + 0][row] = v.x; As[kq + 1][row] = v.y;
            As[kq + 2][row] = v.z; As[kq + 3][row] = v.w;
        }
        #pragma unroll
        for (int i = 0; i < 2; i++) {
            int idx = tid + i * 256;
            int row = idx >> 5;
            int cq  = (idx & 31) * 4;
            *(float4*)&Bs[row][cq] = *(const float4*)&W[(size_t)(k0 + row) * BN + cq];
        }
        __syncthreads();
        #pragma unroll
        for (int k = 0; k < BK; k++) {
            float4 a4  = *(float4*)&As[k][ty * 4];
            float4 b40 = *(float4*)&Bs[k][tx * 8];
            float4 b41 = *(float4*)&Bs[k][tx * 8 + 4];
            float a[4] = {a4.x, a4.y, a4.z, a4.w};
            float b[8] = {b40.x, b40.y, b40.z, b40.w, b41.x, b41.y, b41.z, b41.w};
            #pragma unroll
            for (int r = 0; r < 4; r++)
                #pragma unroll
                for (int j = 0; j < 8; j++) acc[r][j] += a[r] * b[j];
        }
        __syncthreads();
    }
    #pragma unroll
    for (int r = 0; r < 4; r++) {
        int m = m0 + ty * 4 + r;
        if (m < N_NODES) {
            *(float4*)&g_h1[(size_t)m * C1 + tx * 8] =
                make_float4(acc[r][0], acc[r][1], acc[r][2], acc[r][3]);
            *(float4*)&g_h1[(size_t)m * C1 + tx * 8 + 4] =
                make_float4(acc[r][4], acc[r][5], acc[r][6], acc[r][7]);
        }
    }
}

// ---------------- K1b: per-node attention logits (layer 1) ------------------
__global__ void al1_kernel(const float* __restrict__ a_s,
                           const float* __restrict__ a_d) {
    int n    = blockIdx.x * 8 + (threadIdx.x >> 5);
    int lane = threadIdx.x & 31;
    if (n >= N_NODES) return;
    float4 hv = *(const float4*)&g_h1[(size_t)n * C1 + lane * 4];
    float4 s4 = *(const float4*)&a_s[lane * 4];
    float4 d4 = *(const float4*)&a_d[lane * 4];
    float vs = hv.x * s4.x + hv.y * s4.y + hv.z * s4.z + hv.w * s4.w;
    float vd = hv.x * d4.x + hv.y * d4.y + hv.z * d4.z + hv.w * d4.w;
    #pragma unroll
    for (int m = 4; m > 0; m >>= 1) {
        vs += __shfl_xor_sync(0xffffffffu, vs, m, 8);
        vd += __shfl_xor_sync(0xffffffffu, vd, m, 8);
    }
    if ((lane & 7) == 0) {
        int h = lane >> 3;
        g_als1[n * HEADS + h] = vs;
        g_ald1[n * HEADS + h] = vd;
    }
}

// ---------------- K2: layer-1 aggregation (warp/node gather, atomic-free) ---
// Fused: unnormalized softmax-weighted sum + normalize + bias + ELU + permute.
__global__ void agg1_kernel(const float* __restrict__ b1) {
    int n = blockIdx.x * 8 + (threadIdx.x >> 5);
    if (n >= N_NODES) return;
    int lane = threadIdx.x & 31;
    int h = lane >> 3;
    int start = g_rowptr[n], end = g_rowptr[n + 1];
    float ald = g_ald1[n * HEADS + h];
    float ax = 0.f, ay = 0.f, az = 0.f, aw = 0.f, wsum = 0.f;

    int j = start;
    for (; j + 2 <= end; j += 2) {
        int s0 = g_csr_src[j], s1 = g_csr_src[j + 1];
        float al0 = g_als1[s0 * HEADS + h];
        float al1 = g_als1[s1 * HEADS + h];
        float4 h0 = *(const float4*)&g_h1[(size_t)s0 * C1 + lane * 4];
        float4 h1v = *(const float4*)&g_h1[(size_t)s1 * C1 + lane * 4];
        float z0 = al0 + ald; z0 = z0 > 0.f ? z0 : 0.2f * z0;
        float z1 = al1 + ald; z1 = z1 > 0.f ? z1 : 0.2f * z1;
        float w0 = __expf(z0), w1 = __expf(z1);
        wsum += w0 + w1;
        ax += h0.x * w0 + h1v.x * w1;
        ay += h0.y * w0 + h1v.y * w1;
        az += h0.z * w0 + h1v.z * w1;
        aw += h0.w * w0 + h1v.w * w1;
    }
    if (j < end) {
        int s0 = g_csr_src[j];
        float al0 = g_als1[s0 * HEADS + h];
        float4 h0 = *(const float4*)&g_h1[(size_t)s0 * C1 + lane * 4];
        float z0 = al0 + ald; z0 = z0 > 0.f ? z0 : 0.2f * z0;
        float w0 = __expf(z0);
        wsum += w0;
        ax += h0.x * w0; ay += h0.y * w0; az += h0.z * w0; aw += h0.w * w0;
    }

    float inv = 1.f / (wsum + 1e-16f);
    int c0 = lane * 4;
    float4 b = *(const float4*)&b1[c0];
    float r[4] = {ax * inv + b.x, ay * inv + b.y,
                  az * inv + b.z, aw * inv + b.w};
    #pragma unroll
    for (int i = 0; i < 4; i++) {
        float t = r[i];
        t = t > 0.f ? t : expm1f(t);
        int cc = c0 + i;
        int jj = (cc & 3) * 32 + (cc >> 2);   // strided regroup
        g_h1p[(size_t)n * C1 + jj] = t;
    }
}

// ---------------- K4: h2 = h1p @ W2 (+ layer-2 logits) ----------------------
__global__ void gemm2_kernel(const float* __restrict__ W2,
                             const float* __restrict__ a_s,
                             const float* __restrict__ a_d) {
    __shared__ float Ws[128 * 16];
    __shared__ float Hs[16][129];
    __shared__ float as2[16], ad2[16];
    int tid = threadIdx.x;            // 256
    int tx = tid & 15, ty = tid >> 4;
    int n0 = blockIdx.x * 16;
    for (int i = tid; i < 128 * 16; i += 256) Ws[i] = W2[i];
    if (tid < 16) { as2[tid] = a_s[tid]; ad2[tid] = a_d[tid]; }
    for (int i = tid; i < 16 * 128; i += 256) {
        int r = i >> 7, cidx = i & 127;
        Hs[r][cidx] = (n0 + r < N_NODES) ? g_h1p[(size_t)(n0 + r) * C1 + cidx] : 0.f;
    }
    __syncthreads();
    float v = 0.f;
    #pragma unroll
    for (int k = 0; k < 128; k++) v += Hs[ty][k] * Ws[k * 16 + tx];
    float vs = v * as2[tx], vd = v * ad2[tx];
    #pragma unroll
    for (int m = 8; m > 0; m >>= 1) {
        vs += __shfl_xor_sync(0xffffffffu, vs, m, 16);
        vd += __shfl_xor_sync(0xffffffffu, vd, m, 16);
    }
    int n = n0 + ty;
    if (n < N_NODES) {
        g_h2[n * OUT_C + tx] = v;
        if (tx == 0) { g_als2[n] = vs; g_ald2[n] = vd; }
    }
}

// ---------------- K5: layer-2 aggregation + bias + log_softmax --------------
// warp/node; half-warp per edge (2 edges in flight), 16 channels each.
__global__ void agg2_kernel(const float* __restrict__ b2,
                            float* __restrict__ out) {
    int n = blockIdx.x * 8 + (threadIdx.x >> 5);
    if (n >= N_NODES) return;
    int lane = threadIdx.x & 31;
    int half = lane >> 4;
    int l16  = lane & 15;
    int start = g_rowptr[n], end = g_rowptr[n + 1];
    float ald = g_ald2[n];
    float acc = 0.f, wsum = 0.f;

    for (int j = start + half; j < end; j += 2) {
        int src = g_csr_src[j];
        float als = g_als2[src];
        float z = als + ald; z = z > 0.f ? z : 0.2f * z;
        float w = __expf(z);
        wsum += w;
        acc += g_h2[src * OUT_C + l16] * w;
    }
    acc  += __shfl_down_sync(0xffffffffu, acc, 16);
    wsum += __shfl_down_sync(0xffffffffu, wsum, 16);
    if (half == 0) {
        float v = acc / (wsum + 1e-16f) + b2[l16];
        float m = v;
        #pragma unroll
        for (int s = 8; s > 0; s >>= 1)
            m = fmaxf(m, __shfl_xor_sync(0x0000ffffu, m, s, 16));
        float ev = __expf(v - m);
        float sum = ev;
        #pragma unroll
        for (int s = 8; s > 0; s >>= 1)
            sum += __shfl_xor_sync(0x0000ffffu, sum, s, 16);
        out[n * OUT_C + l16] = v - m - logf(sum);
    }
}

// ---------------- launcher ---------------------------------------------------
extern "C" void kernel_launch(void* const* d_in, const int* in_sizes, int n_in,
                              void* d_out, int out_size) {
    const float* x      = (const float*)d_in[0];
    const int*   ei     = (const int*)  d_in[1];
    const float* W1     = (const float*)d_in[2];
    const float* a_src1 = (const float*)d_in[3];
    const float* a_dst1 = (const float*)d_in[4];
    const float* b1     = (const float*)d_in[5];
    const float* W2     = (const float*)d_in[6];
    const float* a_src2 = (const float*)d_in[7];
    const float* a_dst2 = (const float*)d_in[8];
    const float* b2     = (const float*)d_in[9];
    float* out = (float*)d_out;

    // CSR build (overlappable with gemm1 on the same stream order)
    zero_cnt_kernel<<<(N_NODES + 255) / 256, 256>>>();
    hist_kernel    <<<(ET + 255) / 256, 256>>>(ei);
    scan1_kernel   <<<NCH, CHUNK>>>();
    scan2_kernel   <<<1, 256>>>();
    scan3_kernel   <<<(N_NODES + 255) / 256, 256>>>();
    scatter_kernel <<<(ET + 255) / 256, 256>>>(ei);

    gemm1_kernel <<<(N_NODES + BM - 1) / BM, 256>>>(x, W1);
    al1_kernel   <<<(N_NODES + 7) / 8, 256>>>(a_src1, a_dst1);
    agg1_kernel  <<<(N_NODES + 7) / 8, 256>>>(b1);
    gemm2_kernel <<<(N_NODES + 15) / 16, 256>>>(W2, a_src2, a_dst2);
    agg2_kernel  <<<(N_NODES + 7) / 8, 256>>>(b2, out);
}

// round 4
// speedup vs baseline: 3.4254x; 1.4347x over previous
#include <cuda_runtime.h>
#include <math.h>

#define N_NODES 100000
#define E_EDGES 1600000
#define ET      (E_EDGES + N_NODES)   // 1,700,000 edges incl. self-loops
#define F_IN    128
#define HID     32
#define HEADS   4
#define C1      (HEADS * HID)         // 128
#define OUT_C   16
#define CHUNK   512
#define NCH     ((N_NODES + CHUNK - 1) / CHUNK)   // 196

// ---------------- scratch (static device globals; no allocs allowed) --------
__device__ float g_h1  [N_NODES * C1];      // x @ W1
__device__ float g_als1[N_NODES * HEADS];
__device__ float g_ald1[N_NODES * HEADS];
__device__ float g_h1p [N_NODES * C1];      // layer-1 output, column-permuted
__device__ float g_h2  [N_NODES * OUT_C];
__device__ float g_als2[N_NODES];
__device__ float g_ald2[N_NODES];

// CSR scratch
__device__ int g_cnt   [N_NODES];
__device__ int g_loc   [N_NODES];
__device__ int g_chsum [NCH];
__device__ int g_choff [NCH];
__device__ int g_rowptr[N_NODES + 1];
__device__ int g_cursor[N_NODES];
__device__ int g_csr_src[ET];

// ---------------- CSR build --------------------------------------------------
__global__ void zero_cnt_kernel() {
    int i = blockIdx.x * blockDim.x + threadIdx.x;
    if (i < N_NODES) g_cnt[i] = 0;
}

__global__ void hist_kernel(const int* __restrict__ ei) {
    int e = blockIdx.x * blockDim.x + threadIdx.x;
    if (e >= ET) return;
    int dst = (e < E_EDGES) ? ei[E_EDGES + e] : e - E_EDGES;
    atomicAdd(&g_cnt[dst], 1);
}

__global__ void scan1_kernel() {
    __shared__ int s[CHUNK];
    int t = threadIdx.x;
    int i = blockIdx.x * CHUNK + t;
    int v = (i < N_NODES) ? g_cnt[i] : 0;
    s[t] = v;
    __syncthreads();
    #pragma unroll
    for (int off = 1; off < CHUNK; off <<= 1) {
        int x = (t >= off) ? s[t - off] : 0;
        __syncthreads();
        s[t] += x;
        __syncthreads();
    }
    if (i < N_NODES) g_loc[i] = s[t] - v;
    if (t == CHUNK - 1) g_chsum[blockIdx.x] = s[t];
}

__global__ void scan2_kernel() {
    __shared__ int s[256];
    int t = threadIdx.x;
    int v = (t < NCH) ? g_chsum[t] : 0;
    s[t] = v;
    __syncthreads();
    #pragma unroll
    for (int off = 1; off < 256; off <<= 1) {
        int x = (t >= off) ? s[t - off] : 0;
        __syncthreads();
        s[t] += x;
        __syncthreads();
    }
    if (t < NCH) g_choff[t] = s[t] - v;
}

__global__ void scan3_kernel() {
    int i = blockIdx.x * blockDim.x + threadIdx.x;
    if (i < N_NODES) {
        int r = g_loc[i] + g_choff[i / CHUNK];
        g_rowptr[i] = r;
        g_cursor[i] = r;
    }
    if (i == 0) g_rowptr[N_NODES] = ET;
}

__global__ void scatter_kernel(const int* __restrict__ ei) {
    int e = blockIdx.x * blockDim.x + threadIdx.x;
    if (e >= ET) return;
    int src, dst;
    if (e < E_EDGES) { src = ei[e]; dst = ei[E_EDGES + e]; }
    else             { src = dst = e - E_EDGES; }
    int pos = atomicAdd(&g_cursor[dst], 1);
    g_csr_src[pos] = src;
}

// ---------------- K1: h1 = x @ W1  (128x128x8, 8x8 microtile) ---------------
// Fused epilogue: per-node attention logits (als1/ald1).
__global__ __launch_bounds__(256) void gemm1_kernel(
        const float* __restrict__ A, const float* __restrict__ W,
        const float* __restrict__ a_s, const float* __restrict__ a_d) {
    __shared__ float As[8][128];      // [k][m]
    __shared__ float Bs[8][128];      // [k][n]
    int tid = threadIdx.x;
    int tx = tid & 15, ty = tid >> 4;
    int m0 = blockIdx.x * 128;
    int arow = tid >> 1;              // 0..127
    int akq  = (tid & 1) * 4;
    int brow = tid >> 5;              // 0..7
    int bcol = (tid & 31) * 4;
    float acc[8][8];
    #pragma unroll
    for (int r = 0; r < 8; r++)
        #pragma unroll
        for (int j = 0; j < 8; j++) acc[r][j] = 0.f;

    for (int k0 = 0; k0 < F_IN; k0 += 8) {
        float4 av = make_float4(0.f, 0.f, 0.f, 0.f);
        if (m0 + arow < N_NODES)
            av = *(const float4*)&A[(size_t)(m0 + arow) * F_IN + k0 + akq];
        As[akq + 0][arow] = av.x; As[akq + 1][arow] = av.y;
        As[akq + 2][arow] = av.z; As[akq + 3][arow] = av.w;
        *(float4*)&Bs[brow][bcol] = *(const float4*)&W[(size_t)(k0 + brow) * C1 + bcol];
        __syncthreads();
        #pragma unroll
        for (int k = 0; k < 8; k++) {
            float4 a0 = *(float4*)&As[k][ty * 8];
            float4 a1 = *(float4*)&As[k][ty * 8 + 4];
            float4 b0 = *(float4*)&Bs[k][tx * 8];
            float4 b1 = *(float4*)&Bs[k][tx * 8 + 4];
            float a[8] = {a0.x, a0.y, a0.z, a0.w, a1.x, a1.y, a1.z, a1.w};
            float b[8] = {b0.x, b0.y, b0.z, b0.w, b1.x, b1.y, b1.z, b1.w};
            #pragma unroll
            for (int r = 0; r < 8; r++)
                #pragma unroll
                for (int j = 0; j < 8; j++) acc[r][j] += a[r] * b[j];
        }
        __syncthreads();
    }

    // fused attention-logit epilogue: cols tx*8..+8 lie in head h = tx>>2
    float4 s0 = *(const float4*)&a_s[tx * 8];
    float4 s1 = *(const float4*)&a_s[tx * 8 + 4];
    float4 d0 = *(const float4*)&a_d[tx * 8];
    float4 d1 = *(const float4*)&a_d[tx * 8 + 4];
    float sv[8] = {s0.x, s0.y, s0.z, s0.w, s1.x, s1.y, s1.z, s1.w};
    float dv[8] = {d0.x, d0.y, d0.z, d0.w, d1.x, d1.y, d1.z, d1.w};
    float vs[8], vd[8];
    #pragma unroll
    for (int r = 0; r < 8; r++) {
        float a1v = 0.f, a2v = 0.f;
        #pragma unroll
        for (int j = 0; j < 8; j++) { a1v += acc[r][j] * sv[j]; a2v += acc[r][j] * dv[j]; }
        // reduce over the 4 lanes covering this head (lane%4 == tx%4 groups)
        a1v += __shfl_xor_sync(0xffffffffu, a1v, 1);
        a1v += __shfl_xor_sync(0xffffffffu, a1v, 2);
        a2v += __shfl_xor_sync(0xffffffffu, a2v, 1);
        a2v += __shfl_xor_sync(0xffffffffu, a2v, 2);
        vs[r] = a1v; vd[r] = a2v;
    }
    int h = tx >> 2;
    #pragma unroll
    for (int r = 0; r < 8; r++) {
        int m = m0 + ty * 8 + r;
        if (m < N_NODES) {
            *(float4*)&g_h1[(size_t)m * C1 + tx * 8] =
                make_float4(acc[r][0], acc[r][1], acc[r][2], acc[r][3]);
            *(float4*)&g_h1[(size_t)m * C1 + tx * 8 + 4] =
                make_float4(acc[r][4], acc[r][5], acc[r][6], acc[r][7]);
            if ((tx & 3) == 0) {
                g_als1[m * HEADS + h] = vs[r];
                g_ald1[m * HEADS + h] = vd[r];
            }
        }
    }
}

// ---------------- K2: layer-1 aggregation (warp/node gather, atomic-free) ---
__global__ void agg1_kernel(const float* __restrict__ b1) {
    int n = blockIdx.x * 8 + (threadIdx.x >> 5);
    if (n >= N_NODES) return;
    int lane = threadIdx.x & 31;
    int h = lane >> 3;
    int start = g_rowptr[n], end = g_rowptr[n + 1];
    float ald = g_ald1[n * HEADS + h];
    float ax = 0.f, ay = 0.f, az = 0.f, aw = 0.f, wsum = 0.f;

    int j = start;
    for (; j + 4 <= end; j += 4) {
        int s0 = g_csr_src[j], s1 = g_csr_src[j + 1];
        int s2 = g_csr_src[j + 2], s3 = g_csr_src[j + 3];
        float al0 = g_als1[s0 * HEADS + h];
        float al1 = g_als1[s1 * HEADS + h];
        float al2 = g_als1[s2 * HEADS + h];
        float al3 = g_als1[s3 * HEADS + h];
        float4 h0 = *(const float4*)&g_h1[(size_t)s0 * C1 + lane * 4];
        float4 h1 = *(const float4*)&g_h1[(size_t)s1 * C1 + lane * 4];
        float4 h2 = *(const float4*)&g_h1[(size_t)s2 * C1 + lane * 4];
        float4 h3 = *(const float4*)&g_h1[(size_t)s3 * C1 + lane * 4];
        float z0 = al0 + ald; z0 = z0 > 0.f ? z0 : 0.2f * z0;
        float z1 = al1 + ald; z1 = z1 > 0.f ? z1 : 0.2f * z1;
        float z2 = al2 + ald; z2 = z2 > 0.f ? z2 : 0.2f * z2;
        float z3 = al3 + ald; z3 = z3 > 0.f ? z3 : 0.2f * z3;
        float w0 = __expf(z0), w1 = __expf(z1);
        float w2 = __expf(z2), w3 = __expf(z3);
        wsum += (w0 + w1) + (w2 + w3);
        ax += h0.x * w0 + h1.x * w1 + h2.x * w2 + h3.x * w3;
        ay += h0.y * w0 + h1.y * w1 + h2.y * w2 + h3.y * w3;
        az += h0.z * w0 + h1.z * w1 + h2.z * w2 + h3.z * w3;
        aw += h0.w * w0 + h1.w * w1 + h2.w * w2 + h3.w * w3;
    }
    for (; j < end; j++) {
        int s0 = g_csr_src[j];
        float al0 = g_als1[s0 * HEADS + h];
        float4 h0 = *(const float4*)&g_h1[(size_t)s0 * C1 + lane * 4];
        float z0 = al0 + ald; z0 = z0 > 0.f ? z0 : 0.2f * z0;
        float w0 = __expf(z0);
        wsum += w0;
        ax += h0.x * w0; ay += h0.y * w0; az += h0.z * w0; aw += h0.w * w0;
    }

    float inv = 1.f / (wsum + 1e-16f);
    int c0 = lane * 4;
    float4 b = *(const float4*)&b1[c0];
    float r[4] = {ax * inv + b.x, ay * inv + b.y,
                  az * inv + b.z, aw * inv + b.w};
    #pragma unroll
    for (int i = 0; i < 4; i++) {
        float t = r[i];
        t = t > 0.f ? t : expm1f(t);
        int cc = c0 + i;
        int jj = (cc & 3) * 32 + (cc >> 2);   // strided regroup
        g_h1p[(size_t)n * C1 + jj] = t;
    }
}

// ---------------- K3: h2 = h1p @ W2 (node-per-thread, fused logits) ---------
// Block: 128 threads, 256 nodes (2 per thread). k tiled in 4 chunks of 32.
#define G2K 32
__global__ __launch_bounds__(128) void gemm2_kernel(
        const float* __restrict__ W2,
        const float* __restrict__ a_s, const float* __restrict__ a_d) {
    __shared__ float Hs[256][G2K + 4];
    __shared__ float Ws[C1 * OUT_C];          // 2048 floats
    int tid = threadIdx.x;
    int n0 = blockIdx.x * 256;
    for (int i = tid * 4; i < C1 * OUT_C; i += 128 * 4)
        *(float4*)&Ws[i] = *(const float4*)&W2[i];
    float acc0[OUT_C], acc1[OUT_C];
    #pragma unroll
    for (int o = 0; o < OUT_C; o++) { acc0[o] = 0.f; acc1[o] = 0.f; }

    for (int ch = 0; ch < C1 / G2K; ch++) {
        // load 256 rows x 32 k-cols (2048 float4, 16 per thread, coalesced)
        for (int i = tid; i < 256 * (G2K / 4); i += 128) {
            int r  = i >> 3;
            int c4 = (i & 7) * 4;
            float4 v = make_float4(0.f, 0.f, 0.f, 0.f);
            if (n0 + r < N_NODES)
                v = *(const float4*)&g_h1p[(size_t)(n0 + r) * C1 + ch * G2K + c4];
            *(float4*)&Hs[r][c4] = v;
        }
        __syncthreads();
        #pragma unroll
        for (int kk = 0; kk < G2K; kk += 4) {
            int k = ch * G2K + kk;
            float4 h0 = *(float4*)&Hs[tid][kk];
            float4 h1 = *(float4*)&Hs[tid + 128][kk];
            #pragma unroll
            for (int o4 = 0; o4 < OUT_C; o4 += 4) {
                float4 w0 = *(float4*)&Ws[(k + 0) * OUT_C + o4];
                float4 w1 = *(float4*)&Ws[(k + 1) * OUT_C + o4];
                float4 w2 = *(float4*)&Ws[(k + 2) * OUT_C + o4];
                float4 w3 = *(float4*)&Ws[(k + 3) * OUT_C + o4];
                acc0[o4+0] += h0.x*w0.x + h0.y*w1.x + h0.z*w2.x + h0.w*w3.x;
                acc0[o4+1] += h0.x*w0.y + h0.y*w1.y + h0.z*w2.y + h0.w*w3.y;
                acc0[o4+2] += h0.x*w0.z + h0.y*w1.z + h0.z*w2.z + h0.w*w3.z;
                acc0[o4+3] += h0.x*w0.w + h0.y*w1.w + h0.z*w2.w + h0.w*w3.w;
                acc1[o4+0] += h1.x*w0.x + h1.y*w1.x + h1.z*w2.x + h1.w*w3.x;
                acc1[o4+1] += h1.x*w0.y + h1.y*w1.y + h1.z*w2.y + h1.w*w3.y;
                acc1[o4+2] += h1.x*w0.z + h1.y*w1.z + h1.z*w2.z + h1.w*w3.z;
                acc1[o4+3] += h1.x*w0.w + h1.y*w1.w + h1.z*w2.w + h1.w*w3.w;
            }
        }
        __syncthreads();
    }
    // epilogue: outputs + layer-2 logits (all in registers, no shuffles)
    #pragma unroll
    for (int half = 0; half < 2; half++) {
        int n = n0 + half * 128 + tid;
        if (n >= N_NODES) continue;
        float* a = half ? acc1 : acc0;
        float vs = 0.f, vd = 0.f;
        #pragma unroll
        for (int o = 0; o < OUT_C; o++) { vs += a[o] * a_s[o]; vd += a[o] * a_d[o]; }
        #pragma unroll
        for (int o4 = 0; o4 < OUT_C; o4 += 4)
            *(float4*)&g_h2[n * OUT_C + o4] =
                make_float4(a[o4], a[o4+1], a[o4+2], a[o4+3]);
        g_als2[n] = vs;
        g_ald2[n] = vd;
    }
}

// ---------------- K4: layer-2 aggregation + bias + log_softmax --------------
__global__ void agg2_kernel(const float* __restrict__ b2,
                            float* __restrict__ out) {
    int n = blockIdx.x * 8 + (threadIdx.x >> 5);
    if (n >= N_NODES) return;
    int lane = threadIdx.x & 31;
    int half = lane >> 4;
    int l16  = lane & 15;
    int start = g_rowptr[n], end = g_rowptr[n + 1];
    float ald = g_ald2[n];
    float acc = 0.f, wsum = 0.f;

    for (int j = start + half; j < end; j += 2) {
        int src = g_csr_src[j];
        float als = g_als2[src];
        float z = als + ald; z = z > 0.f ? z : 0.2f * z;
        float w = __expf(z);
        wsum += w;
        acc += g_h2[src * OUT_C + l16] * w;
    }
    acc  += __shfl_down_sync(0xffffffffu, acc, 16);
    wsum += __shfl_down_sync(0xffffffffu, wsum, 16);
    if (half == 0) {
        float v = acc / (wsum + 1e-16f) + b2[l16];
        float m = v;
        #pragma unroll
        for (int s = 8; s > 0; s >>= 1)
            m = fmaxf(m, __shfl_xor_sync(0x0000ffffu, m, s, 16));
        float ev = __expf(v - m);
        float sum = ev;
        #pragma unroll
        for (int s = 8; s > 0; s >>= 1)
            sum += __shfl_xor_sync(0x0000ffffu, sum, s, 16);
        out[n * OUT_C + l16] = v - m - logf(sum);
    }
}

// ---------------- launcher ---------------------------------------------------
extern "C" void kernel_launch(void* const* d_in, const int* in_sizes, int n_in,
                              void* d_out, int out_size) {
    const float* x      = (const float*)d_in[0];
    const int*   ei     = (const int*)  d_in[1];
    const float* W1     = (const float*)d_in[2];
    const float* a_src1 = (const float*)d_in[3];
    const float* a_dst1 = (const float*)d_in[4];
    const float* b1     = (const float*)d_in[5];
    const float* W2     = (const float*)d_in[6];
    const float* a_src2 = (const float*)d_in[7];
    const float* a_dst2 = (const float*)d_in[8];
    const float* b2     = (const float*)d_in[9];
    float* out = (float*)d_out;

    // fork: CSR build on side stream, GEMM1 on main stream (capture-legal
    // fork/join; handles created per call and intentionally never destroyed —
    // kernel_launch runs only a handful of times outside graph replay)
    cudaStream_t s2;
    cudaStreamCreateWithFlags(&s2, cudaStreamNonBlocking);
    cudaEvent_t ev1, ev2;
    cudaEventCreateWithFlags(&ev1, cudaEventDisableTiming);
    cudaEventCreateWithFlags(&ev2, cudaEventDisableTiming);

    cudaEventRecord(ev1, 0);
    cudaStreamWaitEvent(s2, ev1, 0);
    zero_cnt_kernel<<<(N_NODES + 255) / 256, 256, 0, s2>>>();
    hist_kernel    <<<(ET + 255) / 256, 256, 0, s2>>>(ei);
    scan1_kernel   <<<NCH, CHUNK, 0, s2>>>();
    scan2_kernel   <<<1, 256, 0, s2>>>();
    scan3_kernel   <<<(N_NODES + 255) / 256, 256, 0, s2>>>();
    scatter_kernel <<<(ET + 255) / 256, 256, 0, s2>>>(ei);
    cudaEventRecord(ev2, s2);

    gemm1_kernel <<<(N_NODES + 127) / 128, 256>>>(x, W1, a_src1, a_dst1);

    cudaStreamWaitEvent(0, ev2, 0);   // join before the gather
    agg1_kernel  <<<(N_NODES + 7) / 8, 256>>>(b1);
    gemm2_kernel <<<(N_NODES + 255) / 256, 128>>>(W2, a_src2, a_dst2);
    agg2_kernel  <<<(N_NODES + 7) / 8, 256>>>(b2, out);
}

// round 5
// speedup vs baseline: 3.4258x; 1.0001x over previous
#include <cuda_runtime.h>
#include <cuda_bf16.h>
#include <math.h>

#define N_NODES 100000
#define E_EDGES 1600000
#define ET      (E_EDGES + N_NODES)   // 1,700,000 edges incl. self-loops
#define F_IN    128
#define HID     32
#define HEADS   4
#define C1      (HEADS * HID)         // 128
#define OUT_C   16
#define CHUNK   512
#define NCH     ((N_NODES + CHUNK - 1) / CHUNK)   // 196

// ---------------- scratch (static device globals; no allocs allowed) --------
__device__ unsigned g_h1b [N_NODES * 64];   // h1 as bf16x2 (2 ch per uint)
__device__ float g_als1[N_NODES * HEADS];
__device__ float g_ald1[N_NODES * HEADS];
__device__ float g_h1p [N_NODES * C1];      // layer-1 output, column-permuted
__device__ float g_h2  [N_NODES * OUT_C];
__device__ float g_als2[N_NODES];
__device__ float g_ald2[N_NODES];

// CSR scratch
__device__ int g_cnt   [N_NODES];
__device__ int g_loc   [N_NODES];
__device__ int g_chsum [NCH];
__device__ int g_choff [NCH];
__device__ int g_rowptr[N_NODES + 1];
__device__ int g_cursor[N_NODES];
__device__ int g_csr_src[ET];

__device__ __forceinline__ unsigned pack_bf2(float a, float b) {
    __nv_bfloat162 t = __float22bfloat162_rn(make_float2(a, b));
    return *(unsigned*)&t;
}
__device__ __forceinline__ float2 unpack_bf2(unsigned u) {
    return __bfloat1622float2(*(__nv_bfloat162*)&u);
}

// ---------------- CSR build --------------------------------------------------
__global__ void zero_cnt_kernel() {
    int i = blockIdx.x * blockDim.x + threadIdx.x;
    if (i < N_NODES) g_cnt[i] = 0;
}

__global__ void hist_kernel(const int* __restrict__ ei) {
    int e = blockIdx.x * blockDim.x + threadIdx.x;
    if (e >= ET) return;
    int dst = (e < E_EDGES) ? ei[E_EDGES + e] : e - E_EDGES;
    atomicAdd(&g_cnt[dst], 1);
}

__global__ void scan1_kernel() {
    __shared__ int s[CHUNK];
    int t = threadIdx.x;
    int i = blockIdx.x * CHUNK + t;
    int v = (i < N_NODES) ? g_cnt[i] : 0;
    s[t] = v;
    __syncthreads();
    #pragma unroll
    for (int off = 1; off < CHUNK; off <<= 1) {
        int x = (t >= off) ? s[t - off] : 0;
        __syncthreads();
        s[t] += x;
        __syncthreads();
    }
    if (i < N_NODES) g_loc[i] = s[t] - v;
    if (t == CHUNK - 1) g_chsum[blockIdx.x] = s[t];
}

__global__ void scan2_kernel() {
    __shared__ int s[256];
    int t = threadIdx.x;
    int v = (t < NCH) ? g_chsum[t] : 0;
    s[t] = v;
    __syncthreads();
    #pragma unroll
    for (int off = 1; off < 256; off <<= 1) {
        int x = (t >= off) ? s[t - off] : 0;
        __syncthreads();
        s[t] += x;
        __syncthreads();
    }
    if (t < NCH) g_choff[t] = s[t] - v;
}

__global__ void scan3_kernel() {
    int i = blockIdx.x * blockDim.x + threadIdx.x;
    if (i < N_NODES) {
        int r = g_loc[i] + g_choff[i / CHUNK];
        g_rowptr[i] = r;
        g_cursor[i] = r;
    }
    if (i == 0) g_rowptr[N_NODES] = ET;
}

__global__ void scatter_kernel(const int* __restrict__ ei) {
    int e = blockIdx.x * blockDim.x + threadIdx.x;
    if (e >= ET) return;
    int src, dst;
    if (e < E_EDGES) { src = ei[e]; dst = ei[E_EDGES + e]; }
    else             { src = dst = e - E_EDGES; }
    int pos = atomicAdd(&g_cursor[dst], 1);
    g_csr_src[pos] = src;
}

// ---------------- K1: h1 = x @ W1  (128x128x8, 8x8 microtile) ---------------
// Fused epilogue: attention logits (fp32 acc) + bf16 h1 store.
__global__ __launch_bounds__(256) void gemm1_kernel(
        const float* __restrict__ A, const float* __restrict__ W,
        const float* __restrict__ a_s, const float* __restrict__ a_d) {
    __shared__ float As[8][128];      // [k][m]
    __shared__ float Bs[8][128];      // [k][n]
    int tid = threadIdx.x;
    int tx = tid & 15, ty = tid >> 4;
    int m0 = blockIdx.x * 128;
    int arow = tid >> 1;
    int akq  = (tid & 1) * 4;
    int brow = tid >> 5;
    int bcol = (tid & 31) * 4;
    float acc[8][8];
    #pragma unroll
    for (int r = 0; r < 8; r++)
        #pragma unroll
        for (int j = 0; j < 8; j++) acc[r][j] = 0.f;

    for (int k0 = 0; k0 < F_IN; k0 += 8) {
        float4 av = make_float4(0.f, 0.f, 0.f, 0.f);
        if (m0 + arow < N_NODES)
            av = *(const float4*)&A[(size_t)(m0 + arow) * F_IN + k0 + akq];
        As[akq + 0][arow] = av.x; As[akq + 1][arow] = av.y;
        As[akq + 2][arow] = av.z; As[akq + 3][arow] = av.w;
        *(float4*)&Bs[brow][bcol] = *(const float4*)&W[(size_t)(k0 + brow) * C1 + bcol];
        __syncthreads();
        #pragma unroll
        for (int k = 0; k < 8; k++) {
            float4 a0 = *(float4*)&As[k][ty * 8];
            float4 a1 = *(float4*)&As[k][ty * 8 + 4];
            float4 b0 = *(float4*)&Bs[k][tx * 8];
            float4 b1 = *(float4*)&Bs[k][tx * 8 + 4];
            float a[8] = {a0.x, a0.y, a0.z, a0.w, a1.x, a1.y, a1.z, a1.w};
            float b[8] = {b0.x, b0.y, b0.z, b0.w, b1.x, b1.y, b1.z, b1.w};
            #pragma unroll
            for (int r = 0; r < 8; r++)
                #pragma unroll
                for (int j = 0; j < 8; j++) acc[r][j] += a[r] * b[j];
        }
        __syncthreads();
    }

    // fused attention-logit epilogue (fp32): cols tx*8..+8 lie in head tx>>2
    float4 s0 = *(const float4*)&a_s[tx * 8];
    float4 s1 = *(const float4*)&a_s[tx * 8 + 4];
    float4 d0 = *(const float4*)&a_d[tx * 8];
    float4 d1 = *(const float4*)&a_d[tx * 8 + 4];
    float sv[8] = {s0.x, s0.y, s0.z, s0.w, s1.x, s1.y, s1.z, s1.w};
    float dv[8] = {d0.x, d0.y, d0.z, d0.w, d1.x, d1.y, d1.z, d1.w};
    float vs[8], vd[8];
    #pragma unroll
    for (int r = 0; r < 8; r++) {
        float a1v = 0.f, a2v = 0.f;
        #pragma unroll
        for (int j = 0; j < 8; j++) { a1v += acc[r][j] * sv[j]; a2v += acc[r][j] * dv[j]; }
        a1v += __shfl_xor_sync(0xffffffffu, a1v, 1);
        a1v += __shfl_xor_sync(0xffffffffu, a1v, 2);
        a2v += __shfl_xor_sync(0xffffffffu, a2v, 1);
        a2v += __shfl_xor_sync(0xffffffffu, a2v, 2);
        vs[r] = a1v; vd[r] = a2v;
    }
    int h = tx >> 2;
    #pragma unroll
    for (int r = 0; r < 8; r++) {
        int m = m0 + ty * 8 + r;
        if (m < N_NODES) {
            uint4 p;
            p.x = pack_bf2(acc[r][0], acc[r][1]);
            p.y = pack_bf2(acc[r][2], acc[r][3]);
            p.z = pack_bf2(acc[r][4], acc[r][5]);
            p.w = pack_bf2(acc[r][6], acc[r][7]);
            *(uint4*)&g_h1b[(size_t)m * 64 + tx * 4] = p;
            if ((tx & 3) == 0) {
                g_als1[m * HEADS + h] = vs[r];
                g_ald1[m * HEADS + h] = vd[r];
            }
        }
    }
}

// ---------------- K2: layer-1 aggregation (warp/node, bf16 gather) ----------
__global__ void agg1_kernel(const float* __restrict__ b1) {
    int n = blockIdx.x * 8 + (threadIdx.x >> 5);
    if (n >= N_NODES) return;
    int lane = threadIdx.x & 31;
    int h = lane >> 3;
    int start = g_rowptr[n], end = g_rowptr[n + 1];
    float ald = g_ald1[n * HEADS + h];
    float ax = 0.f, ay = 0.f, az = 0.f, aw = 0.f, wsum = 0.f;

    int j = start;
    for (; j + 4 <= end; j += 4) {
        int s[4];
        #pragma unroll
        for (int u = 0; u < 4; u++) s[u] = g_csr_src[j + u];
        float al[4]; uint2 hb[4];
        #pragma unroll
        for (int u = 0; u < 4; u++) {
            al[u] = g_als1[s[u] * HEADS + h];
            hb[u] = *(const uint2*)&g_h1b[(size_t)s[u] * 64 + lane * 2];
        }
        #pragma unroll
        for (int u = 0; u < 4; u++) {
            float z = al[u] + ald; z = z > 0.f ? z : 0.2f * z;
            float w = __expf(z);
            wsum += w;
            float2 p0 = unpack_bf2(hb[u].x);
            float2 p1 = unpack_bf2(hb[u].y);
            ax += p0.x * w; ay += p0.y * w; az += p1.x * w; aw += p1.y * w;
        }
    }
    for (; j < end; j++) {
        int s0 = g_csr_src[j];
        float al0 = g_als1[s0 * HEADS + h];
        uint2 hb = *(const uint2*)&g_h1b[(size_t)s0 * 64 + lane * 2];
        float z = al0 + ald; z = z > 0.f ? z : 0.2f * z;
        float w = __expf(z);
        wsum += w;
        float2 p0 = unpack_bf2(hb.x);
        float2 p1 = unpack_bf2(hb.y);
        ax += p0.x * w; ay += p0.y * w; az += p1.x * w; aw += p1.y * w;
    }

    float inv = 1.f / (wsum + 1e-16f);
    int c0 = lane * 4;
    float4 b = *(const float4*)&b1[c0];
    float r[4] = {ax * inv + b.x, ay * inv + b.y,
                  az * inv + b.z, aw * inv + b.w};
    #pragma unroll
    for (int i = 0; i < 4; i++) {
        float t = r[i];
        t = t > 0.f ? t : expm1f(t);
        int cc = c0 + i;
        int jj = (cc & 3) * 32 + (cc >> 2);   // strided regroup
        g_h1p[(size_t)n * C1 + jj] = t;
    }
}

// ---------------- K3: h2 = h1p @ W2 (node-per-thread, fused logits) ---------
#define G2K 32
__global__ __launch_bounds__(128) void gemm2_kernel(
        const float* __restrict__ W2,
        const float* __restrict__ a_s, const float* __restrict__ a_d) {
    __shared__ float Hs[256][G2K + 4];
    __shared__ float Ws[C1 * OUT_C];
    int tid = threadIdx.x;
    int n0 = blockIdx.x * 256;
    for (int i = tid * 4; i < C1 * OUT_C; i += 128 * 4)
        *(float4*)&Ws[i] = *(const float4*)&W2[i];
    float acc0[OUT_C], acc1[OUT_C];
    #pragma unroll
    for (int o = 0; o < OUT_C; o++) { acc0[o] = 0.f; acc1[o] = 0.f; }

    for (int ch = 0; ch < C1 / G2K; ch++) {
        for (int i = tid; i < 256 * (G2K / 4); i += 128) {
            int r  = i >> 3;
            int c4 = (i & 7) * 4;
            float4 v = make_float4(0.f, 0.f, 0.f, 0.f);
            if (n0 + r < N_NODES)
                v = *(const float4*)&g_h1p[(size_t)(n0 + r) * C1 + ch * G2K + c4];
            *(float4*)&Hs[r][c4] = v;
        }
        __syncthreads();
        #pragma unroll
        for (int kk = 0; kk < G2K; kk += 4) {
            int k = ch * G2K + kk;
            float4 h0 = *(float4*)&Hs[tid][kk];
            float4 h1 = *(float4*)&Hs[tid + 128][kk];
            #pragma unroll
            for (int o4 = 0; o4 < OUT_C; o4 += 4) {
                float4 w0 = *(float4*)&Ws[(k + 0) * OUT_C + o4];
                float4 w1 = *(float4*)&Ws[(k + 1) * OUT_C + o4];
                float4 w2 = *(float4*)&Ws[(k + 2) * OUT_C + o4];
                float4 w3 = *(float4*)&Ws[(k + 3) * OUT_C + o4];
                acc0[o4+0] += h0.x*w0.x + h0.y*w1.x + h0.z*w2.x + h0.w*w3.x;
                acc0[o4+1] += h0.x*w0.y + h0.y*w1.y + h0.z*w2.y + h0.w*w3.y;
                acc0[o4+2] += h0.x*w0.z + h0.y*w1.z + h0.z*w2.z + h0.w*w3.z;
                acc0[o4+3] += h0.x*w0.w + h0.y*w1.w + h0.z*w2.w + h0.w*w3.w;
                acc1[o4+0] += h1.x*w0.x + h1.y*w1.x + h1.z*w2.x + h1.w*w3.x;
                acc1[o4+1] += h1.x*w0.y + h1.y*w1.y + h1.z*w2.y + h1.w*w3.y;
                acc1[o4+2] += h1.x*w0.z + h1.y*w1.z + h1.z*w2.z + h1.w*w3.z;
                acc1[o4+3] += h1.x*w0.w + h1.y*w1.w + h1.z*w2.w + h1.w*w3.w;
            }
        }
        __syncthreads();
    }
    #pragma unroll
    for (int half = 0; half < 2; half++) {
        int n = n0 + half * 128 + tid;
        if (n >= N_NODES) continue;
        float* a = half ? acc1 : acc0;
        float vs = 0.f, vd = 0.f;
        #pragma unroll
        for (int o = 0; o < OUT_C; o++) { vs += a[o] * a_s[o]; vd += a[o] * a_d[o]; }
        #pragma unroll
        for (int o4 = 0; o4 < OUT_C; o4 += 4)
            *(float4*)&g_h2[n * OUT_C + o4] =
                make_float4(a[o4], a[o4+1], a[o4+2], a[o4+3]);
        g_als2[n] = vs;
        g_ald2[n] = vd;
    }
}

// ---------------- K4: layer-2 aggregation + bias + log_softmax --------------
// half-warp per edge stream, unroll 2 (4 edges in flight per warp).
__global__ void agg2_kernel(const float* __restrict__ b2,
                            float* __restrict__ out) {
    int n = blockIdx.x * 8 + (threadIdx.x >> 5);
    if (n >= N_NODES) return;
    int lane = threadIdx.x & 31;
    int half = lane >> 4;
    int l16  = lane & 15;
    int start = g_rowptr[n], end = g_rowptr[n + 1];
    float ald = g_ald2[n];
    float acc = 0.f, wsum = 0.f;

    int j = start + half;
    for (; j + 2 < end; j += 4) {
        int s0 = g_csr_src[j];
        int s1 = g_csr_src[j + 2];
        float al0 = g_als2[s0], al1 = g_als2[s1];
        float v0 = g_h2[s0 * OUT_C + l16];
        float v1 = g_h2[s1 * OUT_C + l16];
        float z0 = al0 + ald; z0 = z0 > 0.f ? z0 : 0.2f * z0;
        float z1 = al1 + ald; z1 = z1 > 0.f ? z1 : 0.2f * z1;
        float w0 = __expf(z0), w1 = __expf(z1);
        wsum += w0 + w1;
        acc += v0 * w0 + v1 * w1;
    }
    if (j < end) {
        int s0 = g_csr_src[j];
        float z = g_als2[s0] + ald; z = z > 0.f ? z : 0.2f * z;
        float w = __expf(z);
        wsum += w;
        acc += g_h2[s0 * OUT_C + l16] * w;
    }
    acc  += __shfl_down_sync(0xffffffffu, acc, 16);
    wsum += __shfl_down_sync(0xffffffffu, wsum, 16);
    if (half == 0) {
        float v = acc / (wsum + 1e-16f) + b2[l16];
        float m = v;
        #pragma unroll
        for (int s = 8; s > 0; s >>= 1)
            m = fmaxf(m, __shfl_xor_sync(0x0000ffffu, m, s, 16));
        float ev = __expf(v - m);
        float sum = ev;
        #pragma unroll
        for (int s = 8; s > 0; s >>= 1)
            sum += __shfl_xor_sync(0x0000ffffu, sum, s, 16);
        out[n * OUT_C + l16] = v - m - logf(sum);
    }
}

// ---------------- launcher ---------------------------------------------------
extern "C" void kernel_launch(void* const* d_in, const int* in_sizes, int n_in,
                              void* d_out, int out_size) {
    const float* x      = (const float*)d_in[0];
    const int*   ei     = (const int*)  d_in[1];
    const float* W1     = (const float*)d_in[2];
    const float* a_src1 = (const float*)d_in[3];
    const float* a_dst1 = (const float*)d_in[4];
    const float* b1     = (const float*)d_in[5];
    const float* W2     = (const float*)d_in[6];
    const float* a_src2 = (const float*)d_in[7];
    const float* a_dst2 = (const float*)d_in[8];
    const float* b2     = (const float*)d_in[9];
    float* out = (float*)d_out;

    // fork: CSR build on side stream, GEMM1 on main stream
    cudaStream_t s2;
    cudaStreamCreateWithFlags(&s2, cudaStreamNonBlocking);
    cudaEvent_t ev1, ev2;
    cudaEventCreateWithFlags(&ev1, cudaEventDisableTiming);
    cudaEventCreateWithFlags(&ev2, cudaEventDisableTiming);

    cudaEventRecord(ev1, 0);
    cudaStreamWaitEvent(s2, ev1, 0);
    zero_cnt_kernel<<<(N_NODES + 255) / 256, 256, 0, s2>>>();
    hist_kernel    <<<(ET + 255) / 256, 256, 0, s2>>>(ei);
    scan1_kernel   <<<NCH, CHUNK, 0, s2>>>();
    scan2_kernel   <<<1, 256, 0, s2>>>();
    scan3_kernel   <<<(N_NODES + 255) / 256, 256, 0, s2>>>();
    scatter_kernel <<<(ET + 255) / 256, 256, 0, s2>>>(ei);
    cudaEventRecord(ev2, s2);

    gemm1_kernel <<<(N_NODES + 127) / 128, 256>>>(x, W1, a_src1, a_dst1);

    cudaStreamWaitEvent(0, ev2, 0);   // join before the gather
    agg1_kernel  <<<(N_NODES + 7) / 8, 256>>>(b1);
    gemm2_kernel <<<(N_NODES + 255) / 256, 128>>>(W2, a_src2, a_dst2);
    agg2_kernel  <<<(N_NODES + 7) / 8, 256>>>(b2, out);
}